// round 1
// baseline (speedup 1.0000x reference)
#include <cuda_runtime.h>
#include <cuda_bf16.h>

// CapsuleRoutingPooling: the reference's softmax is over a singleton axis
// (axis=3, size 1) so the routing coefficients c are identically 1.0 and the
// "routing_iteration" loop never affects the output. The whole op collapses to
//   out[b,c,nh,nw,:] = squash( sum over 2x2 window of inp[b,c,2nh+dh,2nw+dw,:] )
// with squash(s) = (|s|^2/(1+|s|^2)) * s/(|s|+1e-8), norm over D=16.
//
// Shapes (fixed by the dataset): B=16, C=64, H=W=64, D=16, k=2 -> nH=nW=32.
// Pure HBM-streaming: 256 MB read + 64 MB write.

#define D_DIM   16
#define W_DIM   64
#define NW_DIM  32
// row stride in floats between h and h+1: W*D = 1024
#define ROW_STRIDE (W_DIM * D_DIM)

__global__ __launch_bounds__(256, 8)
void capsule_pool_squash_kernel(const float* __restrict__ inp,
                                float* __restrict__ out,
                                int n_vec)  // total output vectors = B*C*nH*nW
{
    int idx = blockIdx.x * blockDim.x + threadIdx.x;
    if (idx >= n_vec) return;

    // idx = ((bc * nH) + nh) * nW + nw
    int nw  = idx & (NW_DIM - 1);         // nW = 32
    int t   = idx >> 5;                   // (bc*nH + nh)
    int nh  = t & 31;                     // nH = 32
    int bc  = t >> 5;

    // input base: ((bc*H + 2*nh)*W + 2*nw)*D
    // H = 64, so bc*H + 2*nh = bc*64 + 2*nh
    long long base = ((long long)(bc * 64 + 2 * nh) * W_DIM + 2 * nw) * D_DIM;

    const float4* r0 = reinterpret_cast<const float4*>(inp + base);
    const float4* r1 = reinterpret_cast<const float4*>(inp + base + ROW_STRIDE);

    // Each row contributes 2 adjacent (w, w+1) D-vectors = 8 float4 chunks:
    // chunks 0..3 = w, 4..7 = w+1. Accumulate s = sum of the 4 window vectors.
    float4 a0, a1, a2, a3;
    {
        float4 p0 = r0[0], p1 = r0[1], p2 = r0[2], p3 = r0[3];
        float4 q0 = r0[4], q1 = r0[5], q2 = r0[6], q3 = r0[7];
        a0.x = p0.x + q0.x; a0.y = p0.y + q0.y; a0.z = p0.z + q0.z; a0.w = p0.w + q0.w;
        a1.x = p1.x + q1.x; a1.y = p1.y + q1.y; a1.z = p1.z + q1.z; a1.w = p1.w + q1.w;
        a2.x = p2.x + q2.x; a2.y = p2.y + q2.y; a2.z = p2.z + q2.z; a2.w = p2.w + q2.w;
        a3.x = p3.x + q3.x; a3.y = p3.y + q3.y; a3.z = p3.z + q3.z; a3.w = p3.w + q3.w;
    }
    {
        float4 p0 = r1[0], p1 = r1[1], p2 = r1[2], p3 = r1[3];
        float4 q0 = r1[4], q1 = r1[5], q2 = r1[6], q3 = r1[7];
        a0.x += p0.x + q0.x; a0.y += p0.y + q0.y; a0.z += p0.z + q0.z; a0.w += p0.w + q0.w;
        a1.x += p1.x + q1.x; a1.y += p1.y + q1.y; a1.z += p1.z + q1.z; a1.w += p1.w + q1.w;
        a2.x += p2.x + q2.x; a2.y += p2.y + q2.y; a2.z += p2.z + q2.z; a2.w += p2.w + q2.w;
        a3.x += p3.x + q3.x; a3.y += p3.y + q3.y; a3.z += p3.z + q3.z; a3.w += p3.w + q3.w;
    }

    // squash along D
    float sq =
        a0.x*a0.x + a0.y*a0.y + a0.z*a0.z + a0.w*a0.w +
        a1.x*a1.x + a1.y*a1.y + a1.z*a1.z + a1.w*a1.w +
        a2.x*a2.x + a2.y*a2.y + a2.z*a2.z + a2.w*a2.w +
        a3.x*a3.x + a3.y*a3.y + a3.z*a3.z + a3.w*a3.w;

    float scale = sq / ((1.0f + sq) * (sqrtf(sq) + 1e-8f));

    a0.x *= scale; a0.y *= scale; a0.z *= scale; a0.w *= scale;
    a1.x *= scale; a1.y *= scale; a1.z *= scale; a1.w *= scale;
    a2.x *= scale; a2.y *= scale; a2.z *= scale; a2.w *= scale;
    a3.x *= scale; a3.y *= scale; a3.z *= scale; a3.w *= scale;

    float4* o = reinterpret_cast<float4*>(out + (long long)idx * D_DIM);
    o[0] = a0; o[1] = a1; o[2] = a2; o[3] = a3;
}

extern "C" void kernel_launch(void* const* d_in, const int* in_sizes, int n_in,
                              void* d_out, int out_size)
{
    const float* inp = (const float*)d_in[0];
    float* out = (float*)d_out;

    int n_vec = out_size / D_DIM;   // B*C*nH*nW = 16*64*32*32 = 1,048,576
    int threads = 256;
    int blocks = (n_vec + threads - 1) / threads;
    capsule_pool_squash_kernel<<<blocks, threads>>>(inp, out, n_vec);
}

// round 4
// speedup vs baseline: 1.7263x; 1.7263x over previous
#include <cuda_runtime.h>
#include <cuda_bf16.h>

// CapsuleRoutingPooling — reduced form (softmax over singleton axis => c ≡ 1):
//   out[b,c,nh,nw,:] = squash( sum over 2x2 window of inp[b,c,2nh+dh,2nw+dw,:] )
// B=16, C=64, H=W=64, D=16, k=2 -> nH=nW=32. 256 MB read + 64 MB write.
//
// Layout: 4 threads per output vector. Thread p of a quad loads float4
// chunks {p, p+4} of each 128B window row -> per-instruction quad accesses are
// contiguous 64B half-lines (4x fewer L1 wavefronts than 1-thread/vector).
// Quad-local shfl.bfly reduces the squared norm; stores are fully coalesced
// (512B contiguous per warp).

#define D_DIM 16

__global__ __launch_bounds__(256, 8)
void capsule_pool_squash_kernel(const float* __restrict__ inp,
                                float* __restrict__ out,
                                int n_thr)   // 4 * n_vec
{
    int g = blockIdx.x * blockDim.x + threadIdx.x;
    if (g >= n_thr) return;

    int p   = g & 3;       // float4 slot within the D=16 vector
    int idx = g >> 2;      // output vector id = ((bc*32)+nh)*32 + nw

    int nw = idx & 31;
    int t  = idx >> 5;
    int nh = t & 31;
    int bc = t >> 5;

    // input base (floats): ((bc*64 + 2*nh)*64 + 2*nw) * 16
    long long base = ((long long)(bc * 64 + 2 * nh) * 64 + 2 * nw) * D_DIM;

    // Window rows: each row contributes 128B = 8 float4 (chunks 0..3 = w,
    // 4..7 = w+1). Row stride = W*D = 1024 floats = 256 float4.
    const float4* r0 = reinterpret_cast<const float4*>(inp + base) + p;
    const float4* r1 = r0 + 256;

    float4 L0 = __ldcs(r0);
    float4 L1 = __ldcs(r0 + 4);
    float4 L2 = __ldcs(r1);
    float4 L3 = __ldcs(r1 + 4);

    float4 a;
    a.x = (L0.x + L1.x) + (L2.x + L3.x);
    a.y = (L0.y + L1.y) + (L2.y + L3.y);
    a.z = (L0.z + L1.z) + (L2.z + L3.z);
    a.w = (L0.w + L1.w) + (L2.w + L3.w);

    // squared norm over D=16: quad reduction (xor 1, xor 2 stay in the quad)
    float part = a.x * a.x + a.y * a.y + a.z * a.z + a.w * a.w;
    part += __shfl_xor_sync(0xFFFFFFFFu, part, 1);
    part += __shfl_xor_sync(0xFFFFFFFFu, part, 2);
    float sq = part;

    float scale = sq / ((1.0f + sq) * (sqrtf(sq) + 1e-8f));

    a.x *= scale; a.y *= scale; a.z *= scale; a.w *= scale;

    // fully coalesced: quad lanes write 64B contiguous per vector
    __stcs(reinterpret_cast<float4*>(out) + (long long)idx * 4 + p, a);
}

extern "C" void kernel_launch(void* const* d_in, const int* in_sizes, int n_in,
                              void* d_out, int out_size)
{
    const float* inp = (const float*)d_in[0];
    float* out = (float*)d_out;

    int n_vec = out_size / D_DIM;     // 1,048,576
    int n_thr = n_vec * 4;            // 4,194,304
    if (n_thr <= 0) return;
    int threads = 256;
    int blocks = (n_thr + threads - 1) / threads;
    capsule_pool_squash_kernel<<<blocks, threads>>>(inp, out, n_thr);
}